// round 2
// baseline (speedup 1.0000x reference)
#include <cuda_runtime.h>
#include <cuda_bf16.h>
#include <cstddef>

// Problem constants (fixed by setup_inputs: x (8192,128) fp32, k=16)
#define NROW 8192
#define DIM  128
#define KTOP 16

// Scratch: endorsed __device__ globals (no runtime allocation).
__device__ float g_xn[NROW * DIM];                      // 4 MB  : normalized rows
__device__ float g_S[(size_t)NROW * NROW];              // 256 MB: full similarity matrix
__device__ float g_rowloss[NROW];                       // per-row loss contributions

// ---------------------------------------------------------------------------
// Phase 1: L2-normalize each row.  One warp per row; 4 floats/lane.
// ---------------------------------------------------------------------------
__global__ void normalize_kernel(const float* __restrict__ x) {
    int row  = blockIdx.x * blockDim.y + threadIdx.y;
    int lane = threadIdx.x;
    const float4* xr = reinterpret_cast<const float4*>(x + (size_t)row * DIM);
    float4 v = xr[lane];
    float ss = v.x * v.x + v.y * v.y + v.z * v.z + v.w * v.w;
    #pragma unroll
    for (int off = 16; off; off >>= 1)
        ss += __shfl_xor_sync(0xffffffffu, ss, off);
    float inv = rsqrtf(ss);
    float4 o;
    o.x = v.x * inv; o.y = v.y * inv; o.z = v.z * inv; o.w = v.w * inv;
    reinterpret_cast<float4*>(g_xn + (size_t)row * DIM)[lane] = o;
}

// ---------------------------------------------------------------------------
// Phase 2: S = xn * xn^T, exploiting symmetry.
// 64x64 tile per block, K staged in 2 chunks of 64 dims.
// Thread (tx,ty) in a 16x16 block computes a 4x4 micro-tile.
// Smem tiles stored transposed [d][row] with pitch 68 -> conflict-free stores
// (lane == row) and 16B-aligned LDS.128 fragment loads in the inner loop.
// ---------------------------------------------------------------------------
__global__ __launch_bounds__(256) void gemm_kernel() {
    const int bx = blockIdx.x;   // j panel
    const int by = blockIdx.y;   // i panel
    if (bx < by) return;         // upper triangle only (write both halves)

    __shared__ float As[64][68];
    __shared__ float Bs[64][68];

    const int tid = threadIdx.x;
    const int tx  = tid & 15;
    const int ty  = tid >> 4;
    const int iBase = by * 64;
    const int jBase = bx * 64;

    float acc[4][4] = {};

    #pragma unroll
    for (int kk = 0; kk < DIM; kk += 64) {
        __syncthreads();   // protect previous chunk's tiles
        // Load 64 rows x 64 dims for A and B panels (transposed into smem).
        #pragma unroll
        for (int ch = 0; ch < 4; ch++) {
            int fidx = tid + ch * 256;       // 0..1023
            int row  = fidx & 63;
            int c4   = fidx >> 6;            // 0..15
            float4 a = *reinterpret_cast<const float4*>(
                &g_xn[(size_t)(iBase + row) * DIM + kk + c4 * 4]);
            As[c4 * 4 + 0][row] = a.x;
            As[c4 * 4 + 1][row] = a.y;
            As[c4 * 4 + 2][row] = a.z;
            As[c4 * 4 + 3][row] = a.w;
            float4 b = *reinterpret_cast<const float4*>(
                &g_xn[(size_t)(jBase + row) * DIM + kk + c4 * 4]);
            Bs[c4 * 4 + 0][row] = b.x;
            Bs[c4 * 4 + 1][row] = b.y;
            Bs[c4 * 4 + 2][row] = b.z;
            Bs[c4 * 4 + 3][row] = b.w;
        }
        __syncthreads();

        #pragma unroll 8
        for (int d = 0; d < 64; d++) {
            float4 a = *reinterpret_cast<const float4*>(&As[d][ty * 4]);
            float4 b = *reinterpret_cast<const float4*>(&Bs[d][tx * 4]);
            acc[0][0] += a.x * b.x; acc[0][1] += a.x * b.y; acc[0][2] += a.x * b.z; acc[0][3] += a.x * b.w;
            acc[1][0] += a.y * b.x; acc[1][1] += a.y * b.y; acc[1][2] += a.y * b.z; acc[1][3] += a.y * b.w;
            acc[2][0] += a.z * b.x; acc[2][1] += a.z * b.y; acc[2][2] += a.z * b.z; acc[2][3] += a.z * b.w;
            acc[3][0] += a.w * b.x; acc[3][1] += a.w * b.y; acc[3][2] += a.w * b.z; acc[3][3] += a.w * b.w;
        }
    }

    // Write S[i,j] (row-major, float4 along j).
    #pragma unroll
    for (int ii = 0; ii < 4; ii++) {
        float4 v;
        v.x = acc[ii][0]; v.y = acc[ii][1]; v.z = acc[ii][2]; v.w = acc[ii][3];
        *reinterpret_cast<float4*>(
            &g_S[(size_t)(iBase + ty * 4 + ii) * NROW + jBase + tx * 4]) = v;
    }
    // Mirror to S[j,i] for off-diagonal panels (float4 along i).
    if (bx != by) {
        #pragma unroll
        for (int jj = 0; jj < 4; jj++) {
            float4 v;
            v.x = acc[0][jj]; v.y = acc[1][jj]; v.z = acc[2][jj]; v.w = acc[3][jj];
            *reinterpret_cast<float4*>(
                &g_S[(size_t)(jBase + tx * 4 + jj) * NROW + iBase + ty * 4]) = v;
        }
    }
}

// ---------------------------------------------------------------------------
// Phase 3: per-row expsum (diag INCLUDED, matching reference) + top-16
// (diag masked).  One warp per row; each lane scans 256 strided values
// keeping a sorted-descending local top-16; then a 16-round warp argmax merge.
// rowloss = k*log(expsum) - sum(top16)  so total loss = sum(rowloss).
// ---------------------------------------------------------------------------
__global__ void rowstats_kernel() {
    int row  = blockIdx.x * blockDim.y + threadIdx.y;
    int lane = threadIdx.x;
    const float* __restrict__ Srow = g_S + (size_t)row * NROW;

    float top[KTOP];
    #pragma unroll
    for (int q = 0; q < KTOP; q++) top[q] = -3.0e38f;

    float esum = 0.0f;
    for (int t = 0; t < NROW / 32; t++) {
        int   j = t * 32 + lane;
        float s = Srow[j];
        esum += __expf(s);
        if (j == row) s = -1.0e30f;          // mask self for top-k only
        if (s > top[KTOP - 1]) {
            // bubble-insert, keeps descending order
            #pragma unroll
            for (int q = 0; q < KTOP; q++) {
                float lo = fminf(top[q], s);
                top[q]   = fmaxf(top[q], s);
                s = lo;
            }
        }
    }

    // warp-reduce expsum
    #pragma unroll
    for (int off = 16; off; off >>= 1)
        esum += __shfl_xor_sync(0xffffffffu, esum, off);

    // 16-round merge of per-lane sorted lists via warp argmax
    float topsum = 0.0f;
    #pragma unroll 1
    for (int t = 0; t < KTOP; t++) {
        float best = top[0];
        int   bl   = lane;
        #pragma unroll
        for (int off = 16; off; off >>= 1) {
            float ov = __shfl_xor_sync(0xffffffffu, best, off);
            int   ol = __shfl_xor_sync(0xffffffffu, bl, off);
            if (ov > best || (ov == best && ol < bl)) { best = ov; bl = ol; }
        }
        topsum += best;
        if (lane == bl) {
            #pragma unroll
            for (int q = 0; q < KTOP - 1; q++) top[q] = top[q + 1];
            top[KTOP - 1] = -3.0e38f;
        }
    }

    if (lane == 0)
        g_rowloss[row] = (float)KTOP * logf(esum) - topsum;
}

// ---------------------------------------------------------------------------
// Phase 4: deterministic single-block tree reduction -> d_out[0]
// ---------------------------------------------------------------------------
__global__ void final_reduce_kernel(float* __restrict__ out) {
    __shared__ float sm[1024];
    int t = threadIdx.x;
    float s = 0.0f;
    for (int i = t; i < NROW; i += 1024) s += g_rowloss[i];
    sm[t] = s;
    __syncthreads();
    #pragma unroll
    for (int st = 512; st; st >>= 1) {
        if (t < st) sm[t] += sm[t + st];
        __syncthreads();
    }
    if (t == 0) out[0] = sm[0];
}

// ---------------------------------------------------------------------------
extern "C" void kernel_launch(void* const* d_in, const int* in_sizes, int n_in,
                              void* d_out, int out_size) {
    const float* x = (const float*)d_in[0];
    (void)in_sizes; (void)n_in; (void)out_size;  // shapes fixed: 8192x128, k=16

    normalize_kernel<<<NROW / 8, dim3(32, 8)>>>(x);
    gemm_kernel<<<dim3(NROW / 64, NROW / 64), 256>>>();
    rowstats_kernel<<<NROW / 8, dim3(32, 8)>>>();
    final_reduce_kernel<<<1, 1024>>>((float*)d_out);
}

// round 4
// speedup vs baseline: 2.0136x; 2.0136x over previous
#include <cuda_runtime.h>
#include <cuda_bf16.h>
#include <cstddef>
#include <cstdint>

// Problem constants (fixed by setup_inputs: x (8192,128) fp32, k=16)
#define NROW 8192
#define DIM  128
#define KTOP 16

// Scratch: __device__ globals (no runtime allocation).
__device__ float g_xn[NROW * DIM];                      // 4 MB  : normalized rows
__device__ float g_S[(size_t)NROW * NROW];              // 256 MB: similarity matrix
__device__ float g_rowloss[NROW];                       // per-row loss contributions

// ---------------------------------------------------------------------------
// Phase 1: L2-normalize each row.  One warp per row; 4 floats/lane.
// ---------------------------------------------------------------------------
__global__ void normalize_kernel(const float* __restrict__ x) {
    int row  = blockIdx.x * blockDim.y + threadIdx.y;
    int lane = threadIdx.x;
    const float4* xr = reinterpret_cast<const float4*>(x + (size_t)row * DIM);
    float4 v = xr[lane];
    float ss = v.x * v.x + v.y * v.y + v.z * v.z + v.w * v.w;
    #pragma unroll
    for (int off = 16; off; off >>= 1)
        ss += __shfl_xor_sync(0xffffffffu, ss, off);
    float inv = rsqrtf(ss);
    float4 o;
    o.x = v.x * inv; o.y = v.y * inv; o.z = v.z * inv; o.w = v.w * inv;
    reinterpret_cast<float4*>(g_xn + (size_t)row * DIM)[lane] = o;
}

// ---------------------------------------------------------------------------
// Phase 2: S = xn * xn^T via tensor cores (tf32 mma.m16n8k8), symmetric.
// 128x128 tile per CTA, full K=128 staged in smem once (135 KB dynamic).
// 8 warps in 4x2; each warp computes m32 x n64 (2 m-frags x 8 n-frags).
// Smem pitch 132 floats -> fragment LDS reads are bank-conflict-free.
// Upper-triangle grid; off-diagonal tiles mirror-store S[j][i] (full 32B
// sectors: 8 lanes write 8 consecutive i per j-row).
// ---------------------------------------------------------------------------
__device__ __forceinline__ unsigned f2tf32(float f) {
    unsigned u;
    asm("cvt.rna.tf32.f32 %0, %1;" : "=r"(u) : "f"(f));
    return u;
}

__global__ __launch_bounds__(256) void gemm_tc_kernel() {
    const int bx = blockIdx.x;   // j panel
    const int by = blockIdx.y;   // i panel
    if (bx < by) return;

    extern __shared__ float smem[];
    float (*As)[132] = reinterpret_cast<float (*)[132]>(smem);              // [m][k]
    float (*Bs)[132] = reinterpret_cast<float (*)[132]>(smem + 128 * 132);  // [n][k]

    const int tid  = threadIdx.x;
    const int warp = tid >> 5;
    const int lane = tid & 31;
    const int wr   = warp >> 1;   // 0..3 : warp row (m)
    const int wc   = warp & 1;    // 0..1 : warp col (n)
    const int tq   = lane >> 2;   // 0..7
    const int tr   = lane & 3;    // 0..3
    const int iBase = by * 128;
    const int jBase = bx * 128;

    // Load full 128x128 A and B panels (4096 float4 each side => 16 chunks
    // of 256 threads), converting fp32 -> tf32 bit patterns.
    #pragma unroll
    for (int ch = 0; ch < 16; ch++) {
        int idx = tid + ch * 256;          // 0..4095 (float4 units)
        int row = idx >> 5;                // 0..127
        int c4  = (idx & 31) << 2;         // 0..124
        float4 a = *reinterpret_cast<const float4*>(
            &g_xn[(size_t)(iBase + row) * DIM + c4]);
        As[row][c4 + 0] = __uint_as_float(f2tf32(a.x));
        As[row][c4 + 1] = __uint_as_float(f2tf32(a.y));
        As[row][c4 + 2] = __uint_as_float(f2tf32(a.z));
        As[row][c4 + 3] = __uint_as_float(f2tf32(a.w));
        float4 b = *reinterpret_cast<const float4*>(
            &g_xn[(size_t)(jBase + row) * DIM + c4]);
        Bs[row][c4 + 0] = __uint_as_float(f2tf32(b.x));
        Bs[row][c4 + 1] = __uint_as_float(f2tf32(b.y));
        Bs[row][c4 + 2] = __uint_as_float(f2tf32(b.z));
        Bs[row][c4 + 3] = __uint_as_float(f2tf32(b.w));
    }
    __syncthreads();

    float acc[2][8][4];
    #pragma unroll
    for (int mi = 0; mi < 2; mi++)
        #pragma unroll
        for (int nj = 0; nj < 8; nj++)
            #pragma unroll
            for (int q = 0; q < 4; q++) acc[mi][nj][q] = 0.0f;

    #pragma unroll
    for (int k8 = 0; k8 < 16; k8++) {
        const int k0 = k8 * 8 + tr;
        unsigned af[2][4], bf[8][2];
        #pragma unroll
        for (int mi = 0; mi < 2; mi++) {
            int r = wr * 32 + mi * 16 + tq;
            af[mi][0] = __float_as_uint(As[r][k0]);
            af[mi][1] = __float_as_uint(As[r + 8][k0]);
            af[mi][2] = __float_as_uint(As[r][k0 + 4]);
            af[mi][3] = __float_as_uint(As[r + 8][k0 + 4]);
        }
        #pragma unroll
        for (int nj = 0; nj < 8; nj++) {
            int c = wc * 64 + nj * 8 + tq;
            bf[nj][0] = __float_as_uint(Bs[c][k0]);
            bf[nj][1] = __float_as_uint(Bs[c][k0 + 4]);
        }
        #pragma unroll
        for (int mi = 0; mi < 2; mi++)
            #pragma unroll
            for (int nj = 0; nj < 8; nj++)
                asm volatile(
                    "mma.sync.aligned.m16n8k8.row.col.f32.tf32.tf32.f32 "
                    "{%0,%1,%2,%3}, {%4,%5,%6,%7}, {%8,%9}, {%0,%1,%2,%3};"
                    : "+f"(acc[mi][nj][0]), "+f"(acc[mi][nj][1]),
                      "+f"(acc[mi][nj][2]), "+f"(acc[mi][nj][3])
                    : "r"(af[mi][0]), "r"(af[mi][1]), "r"(af[mi][2]), "r"(af[mi][3]),
                      "r"(bf[nj][0]), "r"(bf[nj][1]));
    }

    // Store direct (float2 along j) and mirror (scalar, full 32B sectors).
    const bool mirror = (bx != by);
    #pragma unroll
    for (int mi = 0; mi < 2; mi++) {
        #pragma unroll
        for (int nj = 0; nj < 8; nj++) {
            int i0 = iBase + wr * 32 + mi * 16 + tq;
            int j0 = jBase + wc * 64 + nj * 8 + 2 * tr;
            float c0 = acc[mi][nj][0], c1 = acc[mi][nj][1];
            float c2 = acc[mi][nj][2], c3 = acc[mi][nj][3];
            *reinterpret_cast<float2*>(&g_S[(size_t)i0 * NROW + j0]) =
                make_float2(c0, c1);
            *reinterpret_cast<float2*>(&g_S[(size_t)(i0 + 8) * NROW + j0]) =
                make_float2(c2, c3);
            if (mirror) {
                g_S[(size_t)j0 * NROW + i0]           = c0;
                g_S[(size_t)(j0 + 1) * NROW + i0]     = c1;
                g_S[(size_t)j0 * NROW + i0 + 8]       = c2;
                g_S[(size_t)(j0 + 1) * NROW + i0 + 8] = c3;
            }
        }
    }
}

// ---------------------------------------------------------------------------
// Phase 3: per-row expsum (diag included, matching reference) + top-16
// (diag masked).  One warp per row, float4 loads.
// ---------------------------------------------------------------------------
__global__ void rowstats_kernel() {
    int row  = blockIdx.x * blockDim.y + threadIdx.y;
    int lane = threadIdx.x;
    const float* __restrict__ Srow = g_S + (size_t)row * NROW;

    float top[KTOP];
    #pragma unroll
    for (int q = 0; q < KTOP; q++) top[q] = -3.0e38f;

    float esum = 0.0f;
    for (int t = 0; t < NROW / 128; t++) {
        int j0 = t * 128 + lane * 4;
        float4 s4 = *reinterpret_cast<const float4*>(&Srow[j0]);
        float vals[4] = {s4.x, s4.y, s4.z, s4.w};
        #pragma unroll
        for (int e = 0; e < 4; e++) {
            float s = vals[e];
            esum += __expf(s);
            if (j0 + e == row) s = -1.0e30f;   // mask self for top-k only
            if (s > top[KTOP - 1]) {
                #pragma unroll
                for (int q = 0; q < KTOP; q++) {
                    float lo = fminf(top[q], s);
                    top[q]   = fmaxf(top[q], s);
                    s = lo;
                }
            }
        }
    }

    #pragma unroll
    for (int off = 16; off; off >>= 1)
        esum += __shfl_xor_sync(0xffffffffu, esum, off);

    float topsum = 0.0f;
    #pragma unroll 1
    for (int t = 0; t < KTOP; t++) {
        float best = top[0];
        int   bl   = lane;
        #pragma unroll
        for (int off = 16; off; off >>= 1) {
            float ov = __shfl_xor_sync(0xffffffffu, best, off);
            int   ol = __shfl_xor_sync(0xffffffffu, bl, off);
            if (ov > best || (ov == best && ol < bl)) { best = ov; bl = ol; }
        }
        topsum += best;
        if (lane == bl) {
            #pragma unroll
            for (int q = 0; q < KTOP - 1; q++) top[q] = top[q + 1];
            top[KTOP - 1] = -3.0e38f;
        }
    }

    if (lane == 0)
        g_rowloss[row] = (float)KTOP * logf(esum) - topsum;
}

// ---------------------------------------------------------------------------
// Phase 4: deterministic single-block tree reduction -> d_out[0]
// ---------------------------------------------------------------------------
__global__ void final_reduce_kernel(float* __restrict__ out) {
    __shared__ float sm[1024];
    int t = threadIdx.x;
    float s = 0.0f;
    for (int i = t; i < NROW; i += 1024) s += g_rowloss[i];
    sm[t] = s;
    __syncthreads();
    #pragma unroll
    for (int st = 512; st; st >>= 1) {
        if (t < st) sm[t] += sm[t + st];
        __syncthreads();
    }
    if (t == 0) out[0] = sm[0];
}

// ---------------------------------------------------------------------------
extern "C" void kernel_launch(void* const* d_in, const int* in_sizes, int n_in,
                              void* d_out, int out_size) {
    const float* x = (const float*)d_in[0];
    (void)in_sizes; (void)n_in; (void)out_size;  // shapes fixed: 8192x128, k=16

    const int GEMM_SMEM = 2 * 128 * 132 * (int)sizeof(float);  // 135168 B
    cudaFuncSetAttribute(gemm_tc_kernel,
                         cudaFuncAttributeMaxDynamicSharedMemorySize, GEMM_SMEM);

    normalize_kernel<<<NROW / 8, dim3(32, 8)>>>(x);
    gemm_tc_kernel<<<dim3(NROW / 128, NROW / 128), 256, GEMM_SMEM>>>();
    rowstats_kernel<<<NROW / 8, dim3(32, 8)>>>();
    final_reduce_kernel<<<1, 1024>>>((float*)d_out);
}